// round 1
// baseline (speedup 1.0000x reference)
#include <cuda_runtime.h>
#include <math.h>

#define EMB   1024
#define STEPS 64
#define BATCH 256
#define NTOK  (BATCH * STEPS)

// ---------------- scratch (static __device__ — allocation-free) ----------------
__device__ float g_Ziu[(size_t)NTOK * EMB];   // txt @ W_iu^T + b_iu
__device__ float g_Zir[(size_t)NTOK * EMB];   // txt @ W_ir^T + b_ir
__device__ float g_Zi [(size_t)NTOK * EMB];   // txt @ W_i^T  + b_i
__device__ float g_h  [BATCH * EMB];          // hidden state
__device__ float g_u  [BATCH * EMB];          // update gate (current step)
__device__ float g_rh [BATCH * EMB];          // reset * h   (current step)

__device__ __forceinline__ float sigmoid_f(float x) {
    return 1.0f / (1.0f + expf(-x));
}

// ============================================================================
// Kernel 1: x-side projections. C[n, j] = sum_k txt[n,k] * W[j,k] + bias[j]
// One launch, blockIdx.z selects which of the 3 weight sets.
// Tile 128x128, K-tile 16, 256 threads, 8x8 per thread.
// ============================================================================
__global__ void xproj_kernel(const float* __restrict__ txt,
                             const float* __restrict__ W_iu, const float* __restrict__ b_iu,
                             const float* __restrict__ W_ir, const float* __restrict__ b_ir,
                             const float* __restrict__ W_i,  const float* __restrict__ b_i)
{
    const float* W;
    const float* bias;
    float* out;
    if (blockIdx.z == 0)      { W = W_iu; bias = b_iu; out = g_Ziu; }
    else if (blockIdx.z == 1) { W = W_ir; bias = b_ir; out = g_Zir; }
    else                      { W = W_i;  bias = b_i;  out = g_Zi;  }

    __shared__ float As[16][128];
    __shared__ float Bs[16][128];

    const int tid = threadIdx.x;
    const int tx  = tid & 15;        // 0..15  -> N
    const int ty  = tid >> 4;        // 0..15  -> M
    const int m0  = blockIdx.x * 128;
    const int n0  = blockIdx.y * 128;

    const float* Ag = txt + (size_t)m0 * EMB;
    const float* Bg = W   + (size_t)n0 * EMB;

    float acc[8][8];
#pragma unroll
    for (int i = 0; i < 8; i++)
#pragma unroll
        for (int j = 0; j < 8; j++) acc[i][j] = 0.0f;

    for (int k0 = 0; k0 < EMB; k0 += 16) {
        // Load A & B tiles (128 rows x 16 k), transpose into [k][row].
#pragma unroll
        for (int it = 0; it < 2; ++it) {
            const int idx = tid + it * 256;          // 0..511
            const int row = idx >> 2;
            const int kf  = (idx & 3) << 2;
            float4 va = *(const float4*)(Ag + (size_t)row * EMB + k0 + kf);
            As[kf + 0][row] = va.x; As[kf + 1][row] = va.y;
            As[kf + 2][row] = va.z; As[kf + 3][row] = va.w;
            float4 vb = *(const float4*)(Bg + (size_t)row * EMB + k0 + kf);
            Bs[kf + 0][row] = vb.x; Bs[kf + 1][row] = vb.y;
            Bs[kf + 2][row] = vb.z; Bs[kf + 3][row] = vb.w;
        }
        __syncthreads();

#pragma unroll
        for (int kk = 0; kk < 16; ++kk) {
            float a[8], b[8];
            *(float4*)(a)     = *(const float4*)&As[kk][ty * 8];
            *(float4*)(a + 4) = *(const float4*)&As[kk][ty * 8 + 4];
            *(float4*)(b)     = *(const float4*)&Bs[kk][tx * 8];
            *(float4*)(b + 4) = *(const float4*)&Bs[kk][tx * 8 + 4];
#pragma unroll
            for (int i = 0; i < 8; i++)
#pragma unroll
                for (int j = 0; j < 8; j++)
                    acc[i][j] += a[i] * b[j];
        }
        __syncthreads();
    }

#pragma unroll
    for (int i = 0; i < 8; i++) {
        const int m = m0 + ty * 8 + i;
        float* orow = out + (size_t)m * EMB + n0 + tx * 8;
#pragma unroll
        for (int j = 0; j < 8; j++) {
            const int n = n0 + tx * 8 + j;
            orow[j] = acc[i][j] + bias[n];
        }
    }
}

// ============================================================================
// Kernel 2: step 0 — h0 = tanh(Zi[:, 0]); write to g_h and out[:, 0, :]
// ============================================================================
__global__ void step0_kernel(float* __restrict__ out)
{
    const int e = blockIdx.x * blockDim.x + threadIdx.x;  // 0 .. BATCH*EMB
    const int b = e >> 10;        // / EMB
    const int j = e & (EMB - 1);  // % EMB
    const float h = tanhf(g_Zi[(size_t)b * STEPS * EMB + j]);
    g_h[e] = h;
    out[(size_t)b * STEPS * EMB + j] = h;
}

// ============================================================================
// Kernel 3: gates — G = h @ [W_hu; W_hr]^T  (M=256, N=2048, K=1024)
// Tile 64x64, K-tile 16, 256 threads, 4x4 per thread.
// Epilogue: n<1024 -> u = sigmoid(G + Ziu_t + b_hu)     -> g_u
//           n>=1024-> r = sigmoid(G + Zir_t + b_hr)     -> g_rh = r*h
// ============================================================================
__global__ void step1_kernel(const float* __restrict__ W_hu, const float* __restrict__ b_hu,
                             const float* __restrict__ W_hr, const float* __restrict__ b_hr,
                             int t)
{
    __shared__ float As[16][64];
    __shared__ float Bs[16][64];

    const int tid = threadIdx.x;
    const int tx  = tid & 15;   // 0..15 -> N
    const int ty  = tid >> 4;   // 0..15 -> M
    const int m0  = blockIdx.x * 64;   // batch
    const int n0  = blockIdx.y * 64;   // 0..2047
    const bool is_r = (n0 >= EMB);
    const float* W  = is_r ? W_hr : W_hu;
    const int nw0   = is_r ? (n0 - EMB) : n0;

    const float* Ag = g_h + (size_t)m0 * EMB;
    const float* Bg = W   + (size_t)nw0 * EMB;

    float acc[4][4];
#pragma unroll
    for (int i = 0; i < 4; i++)
#pragma unroll
        for (int j = 0; j < 4; j++) acc[i][j] = 0.0f;

    for (int k0 = 0; k0 < EMB; k0 += 16) {
        {
            const int row = tid >> 2;
            const int kf  = (tid & 3) << 2;
            float4 va = *(const float4*)(Ag + (size_t)row * EMB + k0 + kf);
            As[kf + 0][row] = va.x; As[kf + 1][row] = va.y;
            As[kf + 2][row] = va.z; As[kf + 3][row] = va.w;
            float4 vb = *(const float4*)(Bg + (size_t)row * EMB + k0 + kf);
            Bs[kf + 0][row] = vb.x; Bs[kf + 1][row] = vb.y;
            Bs[kf + 2][row] = vb.z; Bs[kf + 3][row] = vb.w;
        }
        __syncthreads();

#pragma unroll
        for (int kk = 0; kk < 16; ++kk) {
            float a[4], b[4];
            *(float4*)a = *(const float4*)&As[kk][ty * 4];
            *(float4*)b = *(const float4*)&Bs[kk][tx * 4];
#pragma unroll
            for (int i = 0; i < 4; i++)
#pragma unroll
                for (int j = 0; j < 4; j++)
                    acc[i][j] += a[i] * b[j];
        }
        __syncthreads();
    }

#pragma unroll
    for (int i = 0; i < 4; i++) {
        const int m = m0 + ty * 4 + i;               // batch index
        const size_t zrow = ((size_t)m * STEPS + t) * EMB;
#pragma unroll
        for (int j = 0; j < 4; j++) {
            const int n = n0 + tx * 4 + j;
            if (!is_r) {
                const float u = sigmoid_f(acc[i][j] + g_Ziu[zrow + n] + b_hu[n]);
                g_u[m * EMB + n] = u;
            } else {
                const int nn = n - EMB;
                const float r = sigmoid_f(acc[i][j] + g_Zir[zrow + nn] + b_hr[nn]);
                g_rh[m * EMB + nn] = r * g_h[m * EMB + nn];
            }
        }
    }
}

// ============================================================================
// Kernel 4: candidate + blend — C = (r*h) @ W_h^T  (M=256, N=1024, K=1024)
// Tile 64(M) x 32(N), K-tile 16, 128 threads, 4x4 per thread. Grid 4x32 = 128.
// Epilogue: cand = tanh(C + Zi_t + b_h); h' = u*h + (1-u)*cand
//           -> g_h and out[:, t, :]
// ============================================================================
__global__ void step2_kernel(const float* __restrict__ W_h, const float* __restrict__ b_h,
                             float* __restrict__ out, int t)
{
    __shared__ float As[16][64];
    __shared__ float Bs[16][32];

    const int tid = threadIdx.x;     // 0..127
    const int tx  = tid & 7;         // 0..7  -> N (32 cols)
    const int ty  = tid >> 3;        // 0..15 -> M (64 rows)
    const int m0  = blockIdx.x * 64;
    const int n0  = blockIdx.y * 32;

    const float* Ag = g_rh + (size_t)m0 * EMB;
    const float* Bg = W_h  + (size_t)n0 * EMB;

    float acc[4][4];
#pragma unroll
    for (int i = 0; i < 4; i++)
#pragma unroll
        for (int j = 0; j < 4; j++) acc[i][j] = 0.0f;

    for (int k0 = 0; k0 < EMB; k0 += 16) {
        // A tile: 64 rows x 16 k = 256 float4 slots, 128 threads -> 2 iters
#pragma unroll
        for (int it = 0; it < 2; ++it) {
            const int idx = tid + it * 128;
            const int row = idx >> 2;
            const int kf  = (idx & 3) << 2;
            float4 va = *(const float4*)(Ag + (size_t)row * EMB + k0 + kf);
            As[kf + 0][row] = va.x; As[kf + 1][row] = va.y;
            As[kf + 2][row] = va.z; As[kf + 3][row] = va.w;
        }
        // B tile: 32 rows x 16 k = 128 float4 slots -> 1 iter
        {
            const int row = tid >> 2;
            const int kf  = (tid & 3) << 2;
            float4 vb = *(const float4*)(Bg + (size_t)row * EMB + k0 + kf);
            Bs[kf + 0][row] = vb.x; Bs[kf + 1][row] = vb.y;
            Bs[kf + 2][row] = vb.z; Bs[kf + 3][row] = vb.w;
        }
        __syncthreads();

#pragma unroll
        for (int kk = 0; kk < 16; ++kk) {
            float a[4], b[4];
            *(float4*)a = *(const float4*)&As[kk][ty * 4];
            *(float4*)b = *(const float4*)&Bs[kk][tx * 4];
#pragma unroll
            for (int i = 0; i < 4; i++)
#pragma unroll
                for (int j = 0; j < 4; j++)
                    acc[i][j] += a[i] * b[j];
        }
        __syncthreads();
    }

#pragma unroll
    for (int i = 0; i < 4; i++) {
        const int m = m0 + ty * 4 + i;
        const size_t zrow = ((size_t)m * STEPS + t) * EMB;
#pragma unroll
        for (int j = 0; j < 4; j++) {
            const int n = n0 + tx * 4 + j;
            const float cand = tanhf(acc[i][j] + g_Zi[zrow + n] + b_h[n]);
            const float u = g_u[m * EMB + n];
            const float h = g_h[m * EMB + n];
            const float hn = u * h + (1.0f - u) * cand;
            g_h[m * EMB + n] = hn;
            out[zrow + n] = hn;
        }
    }
}

// ============================================================================
// Host launcher — graph-capturable, allocation-free.
// ============================================================================
extern "C" void kernel_launch(void* const* d_in, const int* in_sizes, int n_in,
                              void* d_out, int out_size)
{
    const float* txt  = (const float*)d_in[0];
    const float* W_iu = (const float*)d_in[1];
    const float* b_iu = (const float*)d_in[2];
    const float* W_hu = (const float*)d_in[3];
    const float* b_hu = (const float*)d_in[4];
    const float* W_ir = (const float*)d_in[5];
    const float* b_ir = (const float*)d_in[6];
    const float* W_hr = (const float*)d_in[7];
    const float* b_hr = (const float*)d_in[8];
    const float* W_i  = (const float*)d_in[9];
    const float* b_i  = (const float*)d_in[10];
    const float* W_h  = (const float*)d_in[11];
    const float* b_h  = (const float*)d_in[12];
    float* out = (float*)d_out;

    // 1. All x-side projections (includes t=0 candidate pre-activation)
    dim3 gx(NTOK / 128, EMB / 128, 3);
    xproj_kernel<<<gx, 256>>>(txt, W_iu, b_iu, W_ir, b_ir, W_i, b_i);

    // 2. h0 = tanh(Zi[:, 0])
    step0_kernel<<<(BATCH * EMB) / 256, 256>>>(out);

    // 3. Recurrence
    for (int t = 1; t < STEPS; ++t) {
        step1_kernel<<<dim3(BATCH / 64, 2 * EMB / 64), 256>>>(W_hu, b_hu, W_hr, b_hr, t);
        step2_kernel<<<dim3(BATCH / 64, EMB / 32), 128>>>(W_h, b_h, out, t);
    }
}

// round 3
// speedup vs baseline: 1.5019x; 1.5019x over previous
#include <cuda_runtime.h>
#include <cuda_bf16.h>
#include <math.h>
#include <stdint.h>

#define EMB   1024
#define STEPS 64
#define BATCH 256
#define NTOK  (BATCH * STEPS)
#define KP    3072   // split K': [hi|lo|hi] x [hi|hi|lo]

// ---------------- static device scratch (allocation-free) ----------------
__device__ __align__(128) __nv_bfloat16 g_txtp[(size_t)NTOK * KP];     // txt split
__device__ __align__(128) __nv_bfloat16 g_Wx[3ull * EMB * KP];         // W_iu, W_ir, W_i split
__device__ __align__(128) __nv_bfloat16 g_Wcat[2ull * EMB * KP];       // [W_hu; W_hr] split
__device__ __align__(128) __nv_bfloat16 g_Whp[(size_t)EMB * KP];       // W_h split
__device__ __align__(128) __nv_bfloat16 g_hp[(size_t)BATCH * KP];      // h split
__device__ __align__(128) __nv_bfloat16 g_rhp[(size_t)BATCH * KP];     // r*h split
__device__ float g_Ziu[(size_t)NTOK * EMB];
__device__ float g_Zir[(size_t)NTOK * EMB];
__device__ float g_Zi [(size_t)NTOK * EMB];
__device__ float g_h[BATCH * EMB];
__device__ float g_u[BATCH * EMB];
__device__ float g_bcat[2 * EMB];

// ---------------- helpers ----------------
__device__ __forceinline__ uint32_t su32(const void* p) {
    return (uint32_t)__cvta_generic_to_shared(p);
}
__device__ __forceinline__ void cpa16(uint32_t s, const void* g) {
    asm volatile("cp.async.cg.shared.global [%0], [%1], 16;\n" :: "r"(s), "l"(g));
}
__device__ __forceinline__ void ldm4(uint32_t& r0, uint32_t& r1, uint32_t& r2, uint32_t& r3, uint32_t a) {
    asm volatile("ldmatrix.sync.aligned.m8n8.x4.shared.b16 {%0,%1,%2,%3}, [%4];\n"
                 : "=r"(r0), "=r"(r1), "=r"(r2), "=r"(r3) : "r"(a));
}
__device__ __forceinline__ void mma16816(float* c, const uint32_t* a, const uint32_t* b) {
    asm volatile("mma.sync.aligned.m16n8k16.row.col.f32.bf16.bf16.f32 "
                 "{%0,%1,%2,%3},{%4,%5,%6,%7},{%8,%9},{%0,%1,%2,%3};\n"
                 : "+f"(c[0]), "+f"(c[1]), "+f"(c[2]), "+f"(c[3])
                 : "r"(a[0]), "r"(a[1]), "r"(a[2]), "r"(a[3]), "r"(b[0]), "r"(b[1]));
}
__device__ __forceinline__ void split2(float x, __nv_bfloat16& hi, __nv_bfloat16& lo) {
    hi = __float2bfloat16(x);
    lo = __float2bfloat16(x - __bfloat162float(hi));
}
__device__ __forceinline__ float sigmoid_f(float x) { return 1.0f / (1.0f + expf(-x)); }

// ---------------- conversion kernels ----------------
// A-side split: dst[row*KP + {0,1024,2048} + col] = {hi, lo, hi}
__global__ void conv_split_A(const float* __restrict__ src) {
    int i = blockIdx.x * blockDim.x + threadIdx.x;          // NTOK*EMB
    int row = i >> 10, col = i & 1023;
    __nv_bfloat16 hi, lo; split2(src[i], hi, lo);
    size_t b = (size_t)row * KP + col;
    g_txtp[b] = hi; g_txtp[b + 1024] = lo; g_txtp[b + 2048] = hi;
}
// B-side split: {hi, hi, lo}; which selects destination
__global__ void conv_split_B(const float* __restrict__ src, int which) {
    int i = blockIdx.x * blockDim.x + threadIdx.x;          // EMB*EMB
    int row = i >> 10, col = i & 1023;
    __nv_bfloat16* dst;
    switch (which) {
        case 0: dst = g_Wx; break;
        case 1: dst = g_Wx + (size_t)EMB * KP; break;
        case 2: dst = g_Wx + 2ull * EMB * KP; break;
        case 3: dst = g_Wcat; break;
        case 4: dst = g_Wcat + (size_t)EMB * KP; break;
        default: dst = g_Whp; break;
    }
    __nv_bfloat16 hi, lo; split2(src[i], hi, lo);
    size_t b = (size_t)row * KP + col;
    dst[b] = hi; dst[b + 1024] = hi; dst[b + 2048] = lo;
}
__global__ void bcat_kernel(const float* __restrict__ b_hu, const float* __restrict__ b_hr) {
    int i = blockIdx.x * blockDim.x + threadIdx.x;          // 2048
    g_bcat[i] = (i < EMB) ? b_hu[i] : b_hr[i - EMB];
}
// h0 = tanh(Zi[:, 0]); writes g_h, g_hp, out[:,0,:]
__global__ void h0_kernel(float* __restrict__ out) {
    int e = blockIdx.x * blockDim.x + threadIdx.x;          // BATCH*EMB
    int b = e >> 10, j = e & 1023;
    size_t zrow = (size_t)b * STEPS * EMB + j;
    float h = tanhf(g_Zi[zrow]);
    g_h[e] = h;
    out[zrow] = h;
    __nv_bfloat16 hi, lo; split2(h, hi, lo);
    size_t bb = (size_t)b * KP + j;
    g_hp[bb] = hi; g_hp[bb + 1024] = lo; g_hp[bb + 2048] = hi;
}

// ---------------- epilogues ----------------
template<int EPI>
__device__ __forceinline__ void epi_write(int m, int n, float v, const float* bias,
                                          float* out, int t, int z) {
    if constexpr (EPI == 0) {
        // xproj: Z = acc + bias
        float* Z = (z == 0) ? g_Ziu : (z == 1) ? g_Zir : g_Zi;
        Z[(size_t)m * EMB + n] = v + bias[n];
    } else if constexpr (EPI == 1) {
        // gates: n<1024 -> u; else -> r, write rh split
        size_t zrow = ((size_t)m * STEPS + t) * EMB;
        if (n < EMB) {
            float u = sigmoid_f(v + g_Ziu[zrow + n] + g_bcat[n]);
            g_u[m * EMB + n] = u;
        } else {
            int nn = n - EMB;
            float r = sigmoid_f(v + g_Zir[zrow + nn] + g_bcat[n]);
            float rh = r * g_h[m * EMB + nn];
            __nv_bfloat16 hi, lo; split2(rh, hi, lo);
            size_t b = (size_t)m * KP + nn;
            g_rhp[b] = hi; g_rhp[b + 1024] = lo; g_rhp[b + 2048] = hi;
        }
    } else {
        // candidate + blend
        size_t zrow = ((size_t)m * STEPS + t) * EMB;
        float cand = tanhf(v + g_Zi[zrow + n] + bias[n]);
        float u = g_u[m * EMB + n];
        float h = g_h[m * EMB + n];
        float hn = u * h + (1.0f - u) * cand;
        out[zrow + n] = hn;
        g_h[m * EMB + n] = hn;
        __nv_bfloat16 hi, lo; split2(hn, hi, lo);
        size_t b = (size_t)m * KP + n;
        g_hp[b] = hi; g_hp[b + 1024] = lo; g_hp[b + 2048] = hi;
    }
}

// ---------------- tensor-core GEMM (bf16 mma.sync, fp32 accum) ----------------
// C[m,n] = sum_k A'[m,k] * B'[n,k], K'=3072. A,B selected by EPI.
template<int BM, int BN, int WARPS_M, int WARPS_N, int EPI>
__global__ void __launch_bounds__(WARPS_M * WARPS_N * 32)
gemm_split(const float* __restrict__ bias0, const float* __restrict__ bias1,
           const float* __restrict__ bias2, float* __restrict__ out, int t)
{
    constexpr int THREADS = WARPS_M * WARPS_N * 32;
    constexpr int BK = 32;
    constexpr int LDS = BK + 8;              // 40 bf16 = 80B row (16B multiple, conflict-free)
    constexpr int WTM = BM / WARPS_M;
    constexpr int WTN = BN / WARPS_N;
    constexpr int MF = WTM / 16;
    constexpr int NF = WTN / 8;
    constexpr int NK = KP / BK;              // 96

    __shared__ __align__(16) __nv_bfloat16 As[2][BM][LDS];
    __shared__ __align__(16) __nv_bfloat16 Bs[2][BN][LDS];

    const int tid  = threadIdx.x;
    const int lane = tid & 31;
    const int wid  = tid >> 5;
    const int wm   = wid % WARPS_M;
    const int wn   = wid / WARPS_M;
    const int m0   = blockIdx.x * BM;
    const int n0   = blockIdx.y * BN;
    const int z    = blockIdx.z;

    const __nv_bfloat16* Ag;
    const __nv_bfloat16* Bg;
    const float* bias = bias0;
    if constexpr (EPI == 0) {
        Ag = g_txtp + (size_t)m0 * KP;
        Bg = g_Wx + (size_t)z * EMB * KP + (size_t)n0 * KP;
        bias = (z == 0) ? bias0 : (z == 1) ? bias1 : bias2;
    } else if constexpr (EPI == 1) {
        Ag = g_hp + (size_t)m0 * KP;
        Bg = g_Wcat + (size_t)n0 * KP;
    } else {
        Ag = g_rhp + (size_t)m0 * KP;
        Bg = g_Whp + (size_t)n0 * KP;
    }

    float acc[MF][NF][4];
#pragma unroll
    for (int mi = 0; mi < MF; mi++)
#pragma unroll
        for (int nj = 0; nj < NF; nj++)
#pragma unroll
            for (int q = 0; q < 4; q++) acc[mi][nj][q] = 0.0f;

    const uint32_t baseA = su32(&As[0][0][0]);
    const uint32_t baseB = su32(&Bs[0][0][0]);
    constexpr uint32_t stA = BM * LDS * 2;
    constexpr uint32_t stB = BN * LDS * 2;

    // ldmatrix lane offsets (relative to stage base), in bytes
    uint32_t offA[MF];
    {
        const int arow = wm * WTM + (lane & 15);
        const int acol = (lane >> 4) << 3;
#pragma unroll
        for (int mi = 0; mi < MF; mi++)
            offA[mi] = ((arow + mi * 16) * LDS + acol) * 2;
    }
    uint32_t offB[NF / 2];
    {
        const int g = lane >> 3;
        const int brow = wn * WTN + (lane & 7) + ((g >> 1) << 3);
        const int bcol = (g & 1) << 3;
#pragma unroll
        for (int p = 0; p < NF / 2; p++)
            offB[p] = ((brow + p * 16) * LDS + bcol) * 2;
    }

    auto load_stage = [&](int s, int k0) {
#pragma unroll
        for (int it = 0; it < (BM * 4) / THREADS; ++it) {
            int c = tid + it * THREADS;
            int row = c >> 2, seg = c & 3;
            cpa16(su32(&As[s][row][seg * 8]), Ag + (size_t)row * KP + k0 + seg * 8);
        }
#pragma unroll
        for (int it = 0; it < (BN * 4) / THREADS; ++it) {
            int c = tid + it * THREADS;
            int row = c >> 2, seg = c & 3;
            cpa16(su32(&Bs[s][row][seg * 8]), Bg + (size_t)row * KP + k0 + seg * 8);
        }
    };

    load_stage(0, 0);
    asm volatile("cp.async.commit_group;\n");

    for (int kt = 0; kt < NK; ++kt) {
        const int p = kt & 1;
        if (kt + 1 < NK) {
            load_stage(1 - p, (kt + 1) * BK);
            asm volatile("cp.async.commit_group;\n");
            asm volatile("cp.async.wait_group 1;\n");
        } else {
            asm volatile("cp.async.wait_group 0;\n");
        }
        __syncthreads();

#pragma unroll
        for (int kk = 0; kk < BK; kk += 16) {
            uint32_t a[MF][4];
#pragma unroll
            for (int mi = 0; mi < MF; mi++)
                ldm4(a[mi][0], a[mi][1], a[mi][2], a[mi][3],
                     baseA + p * stA + offA[mi] + kk * 2);
            uint32_t b[NF][2];
#pragma unroll
            for (int q = 0; q < NF / 2; q++)
                ldm4(b[2 * q][0], b[2 * q][1], b[2 * q + 1][0], b[2 * q + 1][1],
                     baseB + p * stB + offB[q] + kk * 2);
#pragma unroll
            for (int mi = 0; mi < MF; mi++)
#pragma unroll
                for (int nj = 0; nj < NF; nj++)
                    mma16816(acc[mi][nj], a[mi], b[nj]);
        }
        __syncthreads();
    }

    // epilogue
    const int er = lane >> 2;
    const int ec = (lane & 3) * 2;
#pragma unroll
    for (int mi = 0; mi < MF; mi++) {
#pragma unroll
        for (int nj = 0; nj < NF; nj++) {
            int m = m0 + wm * WTM + mi * 16 + er;
            int n = n0 + wn * WTN + nj * 8 + ec;
            float* c = acc[mi][nj];
            epi_write<EPI>(m,     n,     c[0], bias, out, t, z);
            epi_write<EPI>(m,     n + 1, c[1], bias, out, t, z);
            epi_write<EPI>(m + 8, n,     c[2], bias, out, t, z);
            epi_write<EPI>(m + 8, n + 1, c[3], bias, out, t, z);
        }
    }
}

// ---------------- host launcher (graph-capturable, allocation-free) ----------------
extern "C" void kernel_launch(void* const* d_in, const int* in_sizes, int n_in,
                              void* d_out, int out_size)
{
    const float* txt  = (const float*)d_in[0];
    const float* W_iu = (const float*)d_in[1];
    const float* b_iu = (const float*)d_in[2];
    const float* W_hu = (const float*)d_in[3];
    const float* b_hu = (const float*)d_in[4];
    const float* W_ir = (const float*)d_in[5];
    const float* b_ir = (const float*)d_in[6];
    const float* W_hr = (const float*)d_in[7];
    const float* b_hr = (const float*)d_in[8];
    const float* W_i  = (const float*)d_in[9];
    const float* b_i  = (const float*)d_in[10];
    const float* W_h  = (const float*)d_in[11];
    const float* b_h  = (const float*)d_in[12];
    float* out = (float*)d_out;

    // conversions
    conv_split_A<<<(NTOK * EMB) / 256, 256>>>(txt);
    conv_split_B<<<(EMB * EMB) / 256, 256>>>(W_iu, 0);
    conv_split_B<<<(EMB * EMB) / 256, 256>>>(W_ir, 1);
    conv_split_B<<<(EMB * EMB) / 256, 256>>>(W_i,  2);
    conv_split_B<<<(EMB * EMB) / 256, 256>>>(W_hu, 3);
    conv_split_B<<<(EMB * EMB) / 256, 256>>>(W_hr, 4);
    conv_split_B<<<(EMB * EMB) / 256, 256>>>(W_h,  5);
    bcat_kernel<<<(2 * EMB) / 256, 256>>>(b_hu, b_hr);

    // x-side projections: M=16384, N=1024 per weight, z = 3 weights
    gemm_split<128, 128, 4, 2, 0><<<dim3(NTOK / 128, EMB / 128, 3), 256>>>(
        b_iu, b_ir, b_i, nullptr, 0);

    // h0
    h0_kernel<<<(BATCH * EMB) / 256, 256>>>(out);

    // recurrence: step1 = gates (N=2048), step2 = candidate+blend (N=1024)
    for (int t = 1; t < STEPS; ++t) {
        gemm_split<64, 64, 2, 2, 1><<<dim3(BATCH / 64, (2 * EMB) / 64), 128>>>(
            nullptr, nullptr, nullptr, nullptr, t);
        gemm_split<64, 32, 2, 2, 2><<<dim3(BATCH / 64, EMB / 32), 128>>>(
            b_h, nullptr, nullptr, out, t);
    }
}

// round 5
// speedup vs baseline: 1.8689x; 1.2444x over previous
#include <cuda_runtime.h>
#include <cuda_bf16.h>
#include <math.h>
#include <stdint.h>

#define EMB   1024
#define STEPS 64
#define BATCH 256
#define NTOK  (BATCH * STEPS)
#define KS    2048   // stored split K:  [hi | lo]
#define KV    3072   // virtual K: seg0 Ah*Bh, seg1 Al*Bh, seg2 Ah*Bl

// ---------------- static device scratch (allocation-free) ----------------
__device__ __align__(128) __nv_bfloat16 g_txtp[(size_t)NTOK * KS];
__device__ __align__(128) __nv_bfloat16 g_Wx[3ull * EMB * KS];     // W_iu, W_ir, W_i
__device__ __align__(128) __nv_bfloat16 g_Wcat[2ull * EMB * KS];   // [W_hu; W_hr]
__device__ __align__(128) __nv_bfloat16 g_Whp[(size_t)EMB * KS];
__device__ __align__(128) __nv_bfloat16 g_hp[BATCH * KS];
__device__ __align__(128) __nv_bfloat16 g_rhp[BATCH * KS];
__device__ float g_Ziu[(size_t)NTOK * EMB];
__device__ float g_Zir[(size_t)NTOK * EMB];
__device__ float g_Zi [(size_t)NTOK * EMB];
__device__ float g_h[BATCH * EMB];
__device__ float g_u[BATCH * EMB];
__device__ float g_bcat[2 * EMB];

// ---------------- helpers ----------------
__device__ __forceinline__ uint32_t su32(const void* p) {
    return (uint32_t)__cvta_generic_to_shared(p);
}
__device__ __forceinline__ void cpa16(uint32_t s, const void* g) {
    asm volatile("cp.async.cg.shared.global [%0], [%1], 16;\n" :: "r"(s), "l"(g));
}
__device__ __forceinline__ void ldm4(uint32_t& r0, uint32_t& r1, uint32_t& r2, uint32_t& r3, uint32_t a) {
    asm volatile("ldmatrix.sync.aligned.m8n8.x4.shared.b16 {%0,%1,%2,%3}, [%4];\n"
                 : "=r"(r0), "=r"(r1), "=r"(r2), "=r"(r3) : "r"(a));
}
__device__ __forceinline__ void mma16816(float* c, const uint32_t* a, const uint32_t* b) {
    asm volatile("mma.sync.aligned.m16n8k16.row.col.f32.bf16.bf16.f32 "
                 "{%0,%1,%2,%3},{%4,%5,%6,%7},{%8,%9},{%0,%1,%2,%3};\n"
                 : "+f"(c[0]), "+f"(c[1]), "+f"(c[2]), "+f"(c[3])
                 : "r"(a[0]), "r"(a[1]), "r"(a[2]), "r"(a[3]), "r"(b[0]), "r"(b[1]));
}
__device__ __forceinline__ void split2(float x, __nv_bfloat16& hi, __nv_bfloat16& lo) {
    hi = __float2bfloat16(x);
    lo = __float2bfloat16(x - __bfloat162float(hi));
}
__device__ __forceinline__ float sigmoid_f(float x) { return 1.0f / (1.0f + expf(-x)); }

// ---------------- conversion kernels ----------------
// A-side split (txt): [hi|lo], row stride KS. 2 cols per thread, bf162 stores.
__global__ void conv_split_A(const float* __restrict__ src) {
    int i = blockIdx.x * blockDim.x + threadIdx.x;          // float2 index, NTOK*EMB/2
    int row = i >> 9;
    int c2  = (i & 511) << 1;
    float2 v = ((const float2*)src)[i];
    __nv_bfloat16 h0, l0, h1, l1;
    split2(v.x, h0, l0); split2(v.y, h1, l1);
    __nv_bfloat162 hi2; hi2.x = h0; hi2.y = h1;
    __nv_bfloat162 lo2; lo2.x = l0; lo2.y = l1;
    size_t b = (size_t)row * KS + c2;
    *(__nv_bfloat162*)&g_txtp[b]        = hi2;
    *(__nv_bfloat162*)&g_txtp[b + 1024] = lo2;
}
// B-side split (weights): [hi|lo]
__global__ void conv_split_B(const float* __restrict__ src, int which) {
    int i = blockIdx.x * blockDim.x + threadIdx.x;          // float2 index, EMB*EMB/2
    int row = i >> 9;
    int c2  = (i & 511) << 1;
    __nv_bfloat16* dst;
    switch (which) {
        case 0: dst = g_Wx; break;
        case 1: dst = g_Wx + (size_t)EMB * KS; break;
        case 2: dst = g_Wx + 2ull * EMB * KS; break;
        case 3: dst = g_Wcat; break;
        case 4: dst = g_Wcat + (size_t)EMB * KS; break;
        default: dst = g_Whp; break;
    }
    float2 v = ((const float2*)src)[i];
    __nv_bfloat16 h0, l0, h1, l1;
    split2(v.x, h0, l0); split2(v.y, h1, l1);
    __nv_bfloat162 hi2; hi2.x = h0; hi2.y = h1;
    __nv_bfloat162 lo2; lo2.x = l0; lo2.y = l1;
    size_t b = (size_t)row * KS + c2;
    *(__nv_bfloat162*)&dst[b]        = hi2;
    *(__nv_bfloat162*)&dst[b + 1024] = lo2;
}
__global__ void bcat_kernel(const float* __restrict__ b_hu, const float* __restrict__ b_hr) {
    int i = blockIdx.x * blockDim.x + threadIdx.x;
    g_bcat[i] = (i < EMB) ? b_hu[i] : b_hr[i - EMB];
}
__global__ void h0_kernel(float* __restrict__ out) {
    int e = blockIdx.x * blockDim.x + threadIdx.x;          // BATCH*EMB
    int b = e >> 10, j = e & 1023;
    size_t zrow = (size_t)b * STEPS * EMB + j;
    float h = tanhf(g_Zi[zrow]);
    g_h[e] = h;
    out[zrow] = h;
    __nv_bfloat16 hi, lo; split2(h, hi, lo);
    size_t bb = (size_t)b * KS + j;
    g_hp[bb] = hi; g_hp[bb + 1024] = lo;
}

// ---------------- epilogues ----------------
template<int EPI>
__device__ __forceinline__ void epi_write(int m, int n, float v, const float* bias,
                                          float* out, int t, int z) {
    if constexpr (EPI == 0) {
        float* Z = (z == 0) ? g_Ziu : (z == 1) ? g_Zir : g_Zi;
        Z[(size_t)m * EMB + n] = v + bias[n];
    } else if constexpr (EPI == 1) {
        size_t zrow = ((size_t)m * STEPS + t) * EMB;
        if (n < EMB) {
            float u = sigmoid_f(v + g_Ziu[zrow + n] + g_bcat[n]);
            g_u[m * EMB + n] = u;
        } else {
            int nn = n - EMB;
            float r = sigmoid_f(v + g_Zir[zrow + nn] + g_bcat[n]);
            float rh = r * g_h[m * EMB + nn];
            __nv_bfloat16 hi, lo; split2(rh, hi, lo);
            size_t b = (size_t)m * KS + nn;
            g_rhp[b] = hi; g_rhp[b + 1024] = lo;
        }
    } else {
        size_t zrow = ((size_t)m * STEPS + t) * EMB;
        float cand = tanhf(v + g_Zi[zrow + n] + bias[n]);
        float u = g_u[m * EMB + n];
        float h = g_h[m * EMB + n];
        float hn = u * h + (1.0f - u) * cand;
        out[zrow + n] = hn;
        g_h[m * EMB + n] = hn;
        __nv_bfloat16 hi, lo; split2(hn, hi, lo);
        size_t b = (size_t)m * KS + n;
        g_hp[b] = hi; g_hp[b + 1024] = lo;
    }
}

// ---------------- multistage tensor-core GEMM over virtual K=3072 ----------------
template<int BM, int BN, int BK, int S, int WM, int WN, int EPI>
__global__ void __launch_bounds__(WM * WN * 32)
gemm_split(const float* __restrict__ bias0, const float* __restrict__ bias1,
           const float* __restrict__ bias2, float* __restrict__ out, int t)
{
    constexpr int THREADS = WM * WN * 32;
    constexpr int LDS = BK + 8;              // 144B / 272B rows -> conflict-free ldmatrix
    constexpr int WTM = BM / WM;
    constexpr int WTN = BN / WN;
    constexpr int MF = WTM / 16;
    constexpr int NF = WTN / 8;
    constexpr int NK = KV / BK;

    extern __shared__ __align__(16) __nv_bfloat16 sm[];
    __nv_bfloat16* Asm = sm;                      // [S][BM][LDS]
    __nv_bfloat16* Bsm = sm + (size_t)S * BM * LDS;

    const int tid  = threadIdx.x;
    const int lane = tid & 31;
    const int wid  = tid >> 5;
    const int wm   = wid % WM;
    const int wn   = wid / WM;
    const int m0   = blockIdx.x * BM;
    const int n0   = blockIdx.y * BN;
    const int z    = blockIdx.z;

    const __nv_bfloat16* Ag;
    const __nv_bfloat16* Bg;
    const float* bias = bias0;
    if constexpr (EPI == 0) {
        Ag = g_txtp + (size_t)m0 * KS;
        Bg = g_Wx + (size_t)z * EMB * KS + (size_t)n0 * KS;
        bias = (z == 0) ? bias0 : (z == 1) ? bias1 : bias2;
    } else if constexpr (EPI == 1) {
        Ag = g_hp + (size_t)m0 * KS;
        Bg = g_Wcat + (size_t)n0 * KS;
    } else {
        Ag = g_rhp + (size_t)m0 * KS;
        Bg = g_Whp + (size_t)n0 * KS;
    }

    float acc[MF][NF][4];
#pragma unroll
    for (int mi = 0; mi < MF; mi++)
#pragma unroll
        for (int nj = 0; nj < NF; nj++)
#pragma unroll
            for (int q = 0; q < 4; q++) acc[mi][nj][q] = 0.0f;

    // ldmatrix lane offsets (bytes, relative to stage base)
    uint32_t offA[MF];
    {
        const int arow = wm * WTM + (lane & 15);
        const int acol = (lane >> 4) << 3;
#pragma unroll
        for (int mi = 0; mi < MF; mi++)
            offA[mi] = ((arow + mi * 16) * LDS + acol) * 2;
    }
    uint32_t offB[NF / 2];
    {
        const int g = lane >> 3;
        const int brow = wn * WTN + (lane & 7) + ((g >> 1) << 3);
        const int bcol = (g & 1) << 3;
#pragma unroll
        for (int p = 0; p < NF / 2; p++)
            offB[p] = ((brow + p * 16) * LDS + bcol) * 2;
    }

    auto load_stage = [&](int s, int kt) {
        const int k0 = kt * BK;
        const int ak = (k0 < 2048) ? k0 : k0 - 2048;   // A: [hi|lo], hi reused in seg2
        const int bk = (k0 < 1024) ? k0 : k0 - 1024;   // B: [hi|lo], hi reused in seg1
        __nv_bfloat16* a = Asm + (size_t)s * BM * LDS;
        __nv_bfloat16* b = Bsm + (size_t)s * BN * LDS;
        constexpr int SEG = BK / 8;
        constexpr int CA = (BM * SEG) / THREADS;
#pragma unroll
        for (int it = 0; it < CA; ++it) {
            int c = tid + it * THREADS;
            int row = c / SEG, seg = c % SEG;
            cpa16(su32(a + row * LDS + seg * 8), Ag + (size_t)row * KS + ak + seg * 8);
        }
        constexpr int CB = (BN * SEG) / THREADS;
#pragma unroll
        for (int it = 0; it < CB; ++it) {
            int c = tid + it * THREADS;
            int row = c / SEG, seg = c % SEG;
            cpa16(su32(b + row * LDS + seg * 8), Bg + (size_t)row * KS + bk + seg * 8);
        }
    };

#pragma unroll
    for (int s = 0; s < S - 1; ++s) {
        load_stage(s, s);
        asm volatile("cp.async.commit_group;\n" ::);
    }

    for (int kt = 0; kt < NK; ++kt) {
        if (kt + S - 2 < NK) asm volatile("cp.async.wait_group %0;\n" :: "n"(S - 2));
        else                 asm volatile("cp.async.wait_group 0;\n" ::);
        __syncthreads();

        const int nx = kt + S - 1;
        if (nx < NK) {
            load_stage(nx % S, nx);
            asm volatile("cp.async.commit_group;\n" ::);
        }

        const uint32_t pa = su32(Asm + (size_t)(kt % S) * BM * LDS);
        const uint32_t pb = su32(Bsm + (size_t)(kt % S) * BN * LDS);
#pragma unroll
        for (int kk = 0; kk < BK; kk += 16) {
            uint32_t a[MF][4];
#pragma unroll
            for (int mi = 0; mi < MF; mi++)
                ldm4(a[mi][0], a[mi][1], a[mi][2], a[mi][3], pa + offA[mi] + kk * 2);
            uint32_t b[NF][2];
#pragma unroll
            for (int q = 0; q < NF / 2; q++)
                ldm4(b[2 * q][0], b[2 * q][1], b[2 * q + 1][0], b[2 * q + 1][1],
                     pb + offB[q] + kk * 2);
#pragma unroll
            for (int mi = 0; mi < MF; mi++)
#pragma unroll
                for (int nj = 0; nj < NF; nj++)
                    mma16816(acc[mi][nj], a[mi], b[nj]);
        }
    }

    // epilogue
    const int er = lane >> 2;
    const int ec = (lane & 3) * 2;
#pragma unroll
    for (int mi = 0; mi < MF; mi++) {
#pragma unroll
        for (int nj = 0; nj < NF; nj++) {
            int m = m0 + wm * WTM + mi * 16 + er;
            int n = n0 + wn * WTN + nj * 8 + ec;
            float* c = acc[mi][nj];
            epi_write<EPI>(m,     n,     c[0], bias, out, t, z);
            epi_write<EPI>(m,     n + 1, c[1], bias, out, t, z);
            epi_write<EPI>(m + 8, n,     c[2], bias, out, t, z);
            epi_write<EPI>(m + 8, n + 1, c[3], bias, out, t, z);
        }
    }
}

// smem sizes
#define SMEM_XPROJ (3 * (128 + 128) * (64 + 8) * 2)   // 110592
#define SMEM_STEP1 (4 * (64 + 64) * (64 + 8) * 2)     // 73728
#define SMEM_STEP2 (4 * (64 + 32) * (64 + 8) * 2)     // 55296

// ---------------- host launcher (graph-capturable, allocation-free) ----------------
extern "C" void kernel_launch(void* const* d_in, const int* in_sizes, int n_in,
                              void* d_out, int out_size)
{
    const float* txt  = (const float*)d_in[0];
    const float* W_iu = (const float*)d_in[1];
    const float* b_iu = (const float*)d_in[2];
    const float* W_hu = (const float*)d_in[3];
    const float* b_hu = (const float*)d_in[4];
    const float* W_ir = (const float*)d_in[5];
    const float* b_ir = (const float*)d_in[6];
    const float* W_hr = (const float*)d_in[7];
    const float* b_hr = (const float*)d_in[8];
    const float* W_i  = (const float*)d_in[9];
    const float* b_i  = (const float*)d_in[10];
    const float* W_h  = (const float*)d_in[11];
    const float* b_h  = (const float*)d_in[12];
    float* out = (float*)d_out;

    // opt-in to >48KB dynamic smem (idempotent, deterministic)
    cudaFuncSetAttribute((const void*)gemm_split<128, 128, 64, 3, 4, 2, 0>,
                         cudaFuncAttributeMaxDynamicSharedMemorySize, SMEM_XPROJ);
    cudaFuncSetAttribute((const void*)gemm_split<64, 64, 64, 4, 2, 2, 1>,
                         cudaFuncAttributeMaxDynamicSharedMemorySize, SMEM_STEP1);
    cudaFuncSetAttribute((const void*)gemm_split<64, 32, 64, 4, 2, 2, 2>,
                         cudaFuncAttributeMaxDynamicSharedMemorySize, SMEM_STEP2);

    // conversions
    conv_split_A<<<(NTOK * EMB / 2) / 256, 256>>>(txt);
    conv_split_B<<<(EMB * EMB / 2) / 256, 256>>>(W_iu, 0);
    conv_split_B<<<(EMB * EMB / 2) / 256, 256>>>(W_ir, 1);
    conv_split_B<<<(EMB * EMB / 2) / 256, 256>>>(W_i,  2);
    conv_split_B<<<(EMB * EMB / 2) / 256, 256>>>(W_hu, 3);
    conv_split_B<<<(EMB * EMB / 2) / 256, 256>>>(W_hr, 4);
    conv_split_B<<<(EMB * EMB / 2) / 256, 256>>>(W_h,  5);
    bcat_kernel<<<(2 * EMB) / 256, 256>>>(b_hu, b_hr);

    // x-side projections: M=16384, N=1024, 3 weight sets
    gemm_split<128, 128, 64, 3, 4, 2, 0>
        <<<dim3(NTOK / 128, EMB / 128, 3), 256, SMEM_XPROJ>>>(b_iu, b_ir, b_i, nullptr, 0);

    // h0
    h0_kernel<<<(BATCH * EMB) / 256, 256>>>(out);

    // recurrence: gates (N=2048) then candidate+blend (N=1024)
    for (int t = 1; t < STEPS; ++t) {
        gemm_split<64, 64, 64, 4, 2, 2, 1>
            <<<dim3(BATCH / 64, (2 * EMB) / 64), 128, SMEM_STEP1>>>(
                nullptr, nullptr, nullptr, nullptr, t);
        gemm_split<64, 32, 64, 4, 2, 2, 2>
            <<<dim3(BATCH / 64, EMB / 32), 128, SMEM_STEP2>>>(
                b_h, nullptr, nullptr, out, t);
    }
}

// round 6
// speedup vs baseline: 2.0714x; 1.1083x over previous
#include <cuda_runtime.h>
#include <cuda_bf16.h>
#include <math.h>
#include <stdint.h>

#define EMB   1024
#define STEPS 64
#define BATCH 256
#define NTOK  (BATCH * STEPS)
#define KS    2048   // stored split K:  [hi | lo]
#define KV    3072   // virtual K: seg0 Ah*Bh, seg1 Al*Bh, seg2 Ah*Bl
#define RCTAS 128    // persistent recurrence CTAs (<=148 SMs, 1/SM -> co-resident)

// ---------------- static device scratch (allocation-free) ----------------
__device__ __align__(128) __nv_bfloat16 g_txtp[(size_t)NTOK * KS];
__device__ __align__(128) __nv_bfloat16 g_Wx[3ull * EMB * KS];     // W_iu, W_ir, W_i
__device__ __align__(128) __nv_bfloat16 g_Wcat[2ull * EMB * KS];   // [W_hu; W_hr]
__device__ __align__(128) __nv_bfloat16 g_Whp[(size_t)EMB * KS];
__device__ __align__(128) __nv_bfloat16 g_hp[BATCH * KS];
__device__ __align__(128) __nv_bfloat16 g_rhp[BATCH * KS];
__device__ float g_Ziu[(size_t)NTOK * EMB];
__device__ float g_Zir[(size_t)NTOK * EMB];
__device__ float g_Zi [(size_t)NTOK * EMB];
__device__ float g_h[BATCH * EMB];
__device__ float g_u[BATCH * EMB];
__device__ float g_bcat[2 * EMB];
// grid barrier state (arrive resets each barrier; gen monotonic -> replay-safe)
__device__ unsigned g_arrive = 0;
__device__ unsigned g_gen = 0;

// ---------------- helpers ----------------
__device__ __forceinline__ uint32_t su32(const void* p) {
    return (uint32_t)__cvta_generic_to_shared(p);
}
__device__ __forceinline__ void cpa16(uint32_t s, const void* g) {
    asm volatile("cp.async.cg.shared.global [%0], [%1], 16;\n" :: "r"(s), "l"(g));
}
__device__ __forceinline__ void ldm4(uint32_t& r0, uint32_t& r1, uint32_t& r2, uint32_t& r3, uint32_t a) {
    asm volatile("ldmatrix.sync.aligned.m8n8.x4.shared.b16 {%0,%1,%2,%3}, [%4];\n"
                 : "=r"(r0), "=r"(r1), "=r"(r2), "=r"(r3) : "r"(a));
}
__device__ __forceinline__ void mma16816(float* c, const uint32_t* a, const uint32_t* b) {
    asm volatile("mma.sync.aligned.m16n8k16.row.col.f32.bf16.bf16.f32 "
                 "{%0,%1,%2,%3},{%4,%5,%6,%7},{%8,%9},{%0,%1,%2,%3};\n"
                 : "+f"(c[0]), "+f"(c[1]), "+f"(c[2]), "+f"(c[3])
                 : "r"(a[0]), "r"(a[1]), "r"(a[2]), "r"(a[3]), "r"(b[0]), "r"(b[1]));
}
__device__ __forceinline__ void split2(float x, __nv_bfloat16& hi, __nv_bfloat16& lo) {
    hi = __float2bfloat16(x);
    lo = __float2bfloat16(x - __bfloat162float(hi));
}
__device__ __forceinline__ float sigmoid_f(float x) { return 1.0f / (1.0f + expf(-x)); }

// Grid-wide barrier: release/acquire generation counter. Safe because all
// RCTAS CTAs are co-resident (1 CTA/SM, RCTAS <= 148).
__device__ __forceinline__ void grid_barrier() {
    __syncthreads();
    if (threadIdx.x == 0) {
        __threadfence();                               // release CTA's writes
        unsigned gen = *(volatile unsigned*)&g_gen;    // read gen BEFORE arrive
        unsigned old = atomicAdd(&g_arrive, 1);
        if (old == RCTAS - 1) {
            g_arrive = 0;
            __threadfence();
            atomicAdd(&g_gen, 1);
        } else {
            while (*(volatile unsigned*)&g_gen == gen) { __nanosleep(64); }
        }
        __threadfence();                               // acquire
    }
    __syncthreads();
}

// ---------------- conversion kernels ----------------
__global__ void conv_split_A(const float* __restrict__ src) {
    int i = blockIdx.x * blockDim.x + threadIdx.x;          // float2 index
    int row = i >> 9;
    int c2  = (i & 511) << 1;
    float2 v = ((const float2*)src)[i];
    __nv_bfloat16 h0, l0, h1, l1;
    split2(v.x, h0, l0); split2(v.y, h1, l1);
    __nv_bfloat162 hi2; hi2.x = h0; hi2.y = h1;
    __nv_bfloat162 lo2; lo2.x = l0; lo2.y = l1;
    size_t b = (size_t)row * KS + c2;
    *(__nv_bfloat162*)&g_txtp[b]        = hi2;
    *(__nv_bfloat162*)&g_txtp[b + 1024] = lo2;
}
__global__ void conv_split_B(const float* __restrict__ src, int which) {
    int i = blockIdx.x * blockDim.x + threadIdx.x;
    int row = i >> 9;
    int c2  = (i & 511) << 1;
    __nv_bfloat16* dst;
    switch (which) {
        case 0: dst = g_Wx; break;
        case 1: dst = g_Wx + (size_t)EMB * KS; break;
        case 2: dst = g_Wx + 2ull * EMB * KS; break;
        case 3: dst = g_Wcat; break;
        case 4: dst = g_Wcat + (size_t)EMB * KS; break;
        default: dst = g_Whp; break;
    }
    float2 v = ((const float2*)src)[i];
    __nv_bfloat16 h0, l0, h1, l1;
    split2(v.x, h0, l0); split2(v.y, h1, l1);
    __nv_bfloat162 hi2; hi2.x = h0; hi2.y = h1;
    __nv_bfloat162 lo2; lo2.x = l0; lo2.y = l1;
    size_t b = (size_t)row * KS + c2;
    *(__nv_bfloat162*)&dst[b]        = hi2;
    *(__nv_bfloat162*)&dst[b + 1024] = lo2;
}
__global__ void bcat_kernel(const float* __restrict__ b_hu, const float* __restrict__ b_hr) {
    int i = blockIdx.x * blockDim.x + threadIdx.x;
    g_bcat[i] = (i < EMB) ? b_hu[i] : b_hr[i - EMB];
}
__global__ void h0_kernel(float* __restrict__ out) {
    int e = blockIdx.x * blockDim.x + threadIdx.x;
    int b = e >> 10, j = e & 1023;
    size_t zrow = (size_t)b * STEPS * EMB + j;
    float h = tanhf(g_Zi[zrow]);
    g_h[e] = h;
    out[zrow] = h;
    __nv_bfloat16 hi, lo; split2(h, hi, lo);
    size_t bb = (size_t)b * KS + j;
    g_hp[bb] = hi; g_hp[bb + 1024] = lo;
}

// ---------------- epilogues ----------------
template<int EPI>
__device__ __forceinline__ void epi_write(int m, int n, float v, const float* bias,
                                          float* out, int t, int z) {
    if constexpr (EPI == 0) {
        float* Z = (z == 0) ? g_Ziu : (z == 1) ? g_Zir : g_Zi;
        Z[(size_t)m * EMB + n] = v + bias[n];
    } else if constexpr (EPI == 1) {
        size_t zrow = ((size_t)m * STEPS + t) * EMB;
        if (n < EMB) {
            float u = sigmoid_f(v + g_Ziu[zrow + n] + g_bcat[n]);
            g_u[m * EMB + n] = u;
        } else {
            int nn = n - EMB;
            float r = sigmoid_f(v + g_Zir[zrow + nn] + g_bcat[n]);
            float rh = r * g_h[m * EMB + nn];
            __nv_bfloat16 hi, lo; split2(rh, hi, lo);
            size_t b = (size_t)m * KS + nn;
            g_rhp[b] = hi; g_rhp[b + 1024] = lo;
        }
    } else {
        size_t zrow = ((size_t)m * STEPS + t) * EMB;
        float cand = tanhf(v + g_Zi[zrow + n] + bias[n]);
        float u = g_u[m * EMB + n];
        float h = g_h[m * EMB + n];
        float hn = u * h + (1.0f - u) * cand;
        out[zrow + n] = hn;
        g_h[m * EMB + n] = hn;
        __nv_bfloat16 hi, lo; split2(hn, hi, lo);
        size_t b = (size_t)m * KS + n;
        g_hp[b] = hi; g_hp[b + 1024] = lo;
    }
}

// ---------------- one tile-GEMM over virtual K (device fn, 128 threads) ----------
template<int BM, int BN, int EPI>
__device__ __forceinline__ void tile_gemm(const __nv_bfloat16* __restrict__ Ag,
                                          const __nv_bfloat16* __restrict__ Bg,
                                          __nv_bfloat16* sm,
                                          const float* bias, float* out, int t,
                                          int m0, int n0)
{
    constexpr int THREADS = 128;
    constexpr int BK = 64;
    constexpr int S  = 4;
    constexpr int LDS = BK + 8;
    constexpr int WM = 2, WN = 2;
    constexpr int WTM = BM / WM;
    constexpr int WTN = BN / WN;
    constexpr int MF = WTM / 16;
    constexpr int NF = WTN / 8;
    constexpr int NK = KV / BK;

    __nv_bfloat16* Asm = sm;
    __nv_bfloat16* Bsm = sm + (size_t)S * BM * LDS;

    const int tid  = threadIdx.x;
    const int lane = tid & 31;
    const int wid  = tid >> 5;
    const int wm   = wid % WM;
    const int wn   = wid / WM;

    float acc[MF][NF][4];
#pragma unroll
    for (int mi = 0; mi < MF; mi++)
#pragma unroll
        for (int nj = 0; nj < NF; nj++)
#pragma unroll
            for (int q = 0; q < 4; q++) acc[mi][nj][q] = 0.0f;

    uint32_t offA[MF];
    {
        const int arow = wm * WTM + (lane & 15);
        const int acol = (lane >> 4) << 3;
#pragma unroll
        for (int mi = 0; mi < MF; mi++)
            offA[mi] = ((arow + mi * 16) * LDS + acol) * 2;
    }
    uint32_t offB[NF / 2];
    {
        const int g = lane >> 3;
        const int brow = wn * WTN + (lane & 7) + ((g >> 1) << 3);
        const int bcol = (g & 1) << 3;
#pragma unroll
        for (int p = 0; p < NF / 2; p++)
            offB[p] = ((brow + p * 16) * LDS + bcol) * 2;
    }

    auto load_stage = [&](int s, int kt) {
        const int k0 = kt * BK;
        const int ak = (k0 < 2048) ? k0 : k0 - 2048;
        const int bk = (k0 < 1024) ? k0 : k0 - 1024;
        __nv_bfloat16* a = Asm + (size_t)s * BM * LDS;
        __nv_bfloat16* b = Bsm + (size_t)s * BN * LDS;
        constexpr int SEG = BK / 8;
        constexpr int CA = (BM * SEG) / THREADS;
#pragma unroll
        for (int it = 0; it < CA; ++it) {
            int c = tid + it * THREADS;
            int row = c / SEG, seg = c % SEG;
            cpa16(su32(a + row * LDS + seg * 8), Ag + (size_t)row * KS + ak + seg * 8);
        }
        constexpr int CB = (BN * SEG) / THREADS;
#pragma unroll
        for (int it = 0; it < CB; ++it) {
            int c = tid + it * THREADS;
            int row = c / SEG, seg = c % SEG;
            cpa16(su32(b + row * LDS + seg * 8), Bg + (size_t)row * KS + bk + seg * 8);
        }
    };

#pragma unroll
    for (int s = 0; s < S - 1; ++s) {
        load_stage(s, s);
        asm volatile("cp.async.commit_group;\n" ::);
    }

    for (int kt = 0; kt < NK; ++kt) {
        if (kt + S - 2 < NK) asm volatile("cp.async.wait_group %0;\n" :: "n"(S - 2));
        else                 asm volatile("cp.async.wait_group 0;\n" ::);
        __syncthreads();

        const int nx = kt + S - 1;
        if (nx < NK) {
            load_stage(nx % S, nx);
            asm volatile("cp.async.commit_group;\n" ::);
        }

        const uint32_t pa = su32(Asm + (size_t)(kt % S) * BM * LDS);
        const uint32_t pb = su32(Bsm + (size_t)(kt % S) * BN * LDS);
#pragma unroll
        for (int kk = 0; kk < BK; kk += 16) {
            uint32_t a[MF][4];
#pragma unroll
            for (int mi = 0; mi < MF; mi++)
                ldm4(a[mi][0], a[mi][1], a[mi][2], a[mi][3], pa + offA[mi] + kk * 2);
            uint32_t b[NF][2];
#pragma unroll
            for (int q = 0; q < NF / 2; q++)
                ldm4(b[2 * q][0], b[2 * q][1], b[2 * q + 1][0], b[2 * q + 1][1],
                     pb + offB[q] + kk * 2);
#pragma unroll
            for (int mi = 0; mi < MF; mi++)
#pragma unroll
                for (int nj = 0; nj < NF; nj++)
                    mma16816(acc[mi][nj], a[mi], b[nj]);
        }
    }

    const int er = lane >> 2;
    const int ec = (lane & 3) * 2;
#pragma unroll
    for (int mi = 0; mi < MF; mi++) {
#pragma unroll
        for (int nj = 0; nj < NF; nj++) {
            int m = m0 + wm * WTM + mi * 16 + er;
            int n = n0 + wn * WTN + nj * 8 + ec;
            float* c = acc[mi][nj];
            epi_write<EPI>(m,     n,     c[0], bias, out, t, 0);
            epi_write<EPI>(m,     n + 1, c[1], bias, out, t, 0);
            epi_write<EPI>(m + 8, n,     c[2], bias, out, t, 0);
            epi_write<EPI>(m + 8, n + 1, c[3], bias, out, t, 0);
        }
    }
}

// ---------------- persistent recurrence kernel (one launch, all 63 steps) -------
__global__ void __launch_bounds__(128)
rec_persistent(const float* __restrict__ b_h, float* __restrict__ out)
{
    extern __shared__ __align__(16) __nv_bfloat16 sm[];
    const int bid = blockIdx.x;
    const int mA = (bid & 3) * 64, nA = (bid >> 2) * 64;   // gates: 4 x 32 tiles
    const int mB = (bid & 3) * 64, nB = (bid >> 2) * 32;   // cand : 4 x 32 tiles

    for (int t = 1; t < STEPS; ++t) {
        // phase A: gates (u, r) from h
        tile_gemm<64, 64, 1>(g_hp + (size_t)mA * KS, g_Wcat + (size_t)nA * KS,
                             sm, nullptr, nullptr, t, mA, nA);
        grid_barrier();
        // phase B: candidate + blend from r*h
        tile_gemm<64, 32, 2>(g_rhp + (size_t)mB * KS, g_Whp + (size_t)nB * KS,
                             sm, b_h, out, t, mB, nB);
        if (t < STEPS - 1) grid_barrier();
    }
}

// ---------------- xproj multistage GEMM (unchanged from round 5) ----------------
template<int BM, int BN, int BK, int S, int WM, int WN>
__global__ void __launch_bounds__(WM * WN * 32)
xproj_gemm(const float* __restrict__ bias0, const float* __restrict__ bias1,
           const float* __restrict__ bias2)
{
    constexpr int THREADS = WM * WN * 32;
    constexpr int LDS = BK + 8;
    constexpr int WTM = BM / WM;
    constexpr int WTN = BN / WN;
    constexpr int MF = WTM / 16;
    constexpr int NF = WTN / 8;
    constexpr int NK = KV / BK;

    extern __shared__ __align__(16) __nv_bfloat16 sm[];
    __nv_bfloat16* Asm = sm;
    __nv_bfloat16* Bsm = sm + (size_t)S * BM * LDS;

    const int tid  = threadIdx.x;
    const int lane = tid & 31;
    const int wid  = tid >> 5;
    const int wm   = wid % WM;
    const int wn   = wid / WM;
    const int m0   = blockIdx.x * BM;
    const int n0   = blockIdx.y * BN;
    const int z    = blockIdx.z;

    const __nv_bfloat16* Ag = g_txtp + (size_t)m0 * KS;
    const __nv_bfloat16* Bg = g_Wx + (size_t)z * EMB * KS + (size_t)n0 * KS;
    const float* bias = (z == 0) ? bias0 : (z == 1) ? bias1 : bias2;

    float acc[MF][NF][4];
#pragma unroll
    for (int mi = 0; mi < MF; mi++)
#pragma unroll
        for (int nj = 0; nj < NF; nj++)
#pragma unroll
            for (int q = 0; q < 4; q++) acc[mi][nj][q] = 0.0f;

    uint32_t offA[MF];
    {
        const int arow = wm * WTM + (lane & 15);
        const int acol = (lane >> 4) << 3;
#pragma unroll
        for (int mi = 0; mi < MF; mi++)
            offA[mi] = ((arow + mi * 16) * LDS + acol) * 2;
    }
    uint32_t offB[NF / 2];
    {
        const int g = lane >> 3;
        const int brow = wn * WTN + (lane & 7) + ((g >> 1) << 3);
        const int bcol = (g & 1) << 3;
#pragma unroll
        for (int p = 0; p < NF / 2; p++)
            offB[p] = ((brow + p * 16) * LDS + bcol) * 2;
    }

    auto load_stage = [&](int s, int kt) {
        const int k0 = kt * BK;
        const int ak = (k0 < 2048) ? k0 : k0 - 2048;
        const int bk = (k0 < 1024) ? k0 : k0 - 1024;
        __nv_bfloat16* a = Asm + (size_t)s * BM * LDS;
        __nv_bfloat16* b = Bsm + (size_t)s * BN * LDS;
        constexpr int SEG = BK / 8;
        constexpr int CA = (BM * SEG) / THREADS;
#pragma unroll
        for (int it = 0; it < CA; ++it) {
            int c = tid + it * THREADS;
            int row = c / SEG, seg = c % SEG;
            cpa16(su32(a + row * LDS + seg * 8), Ag + (size_t)row * KS + ak + seg * 8);
        }
        constexpr int CB = (BN * SEG) / THREADS;
#pragma unroll
        for (int it = 0; it < CB; ++it) {
            int c = tid + it * THREADS;
            int row = c / SEG, seg = c % SEG;
            cpa16(su32(b + row * LDS + seg * 8), Bg + (size_t)row * KS + bk + seg * 8);
        }
    };

#pragma unroll
    for (int s = 0; s < S - 1; ++s) {
        load_stage(s, s);
        asm volatile("cp.async.commit_group;\n" ::);
    }

    for (int kt = 0; kt < NK; ++kt) {
        if (kt + S - 2 < NK) asm volatile("cp.async.wait_group %0;\n" :: "n"(S - 2));
        else                 asm volatile("cp.async.wait_group 0;\n" ::);
        __syncthreads();

        const int nx = kt + S - 1;
        if (nx < NK) {
            load_stage(nx % S, nx);
            asm volatile("cp.async.commit_group;\n" ::);
        }

        const uint32_t pa = su32(Asm + (size_t)(kt % S) * BM * LDS);
        const uint32_t pb = su32(Bsm + (size_t)(kt % S) * BN * LDS);
#pragma unroll
        for (int kk = 0; kk < BK; kk += 16) {
            uint32_t a[MF][4];
#pragma unroll
            for (int mi = 0; mi < MF; mi++)
                ldm4(a[mi][0], a[mi][1], a[mi][2], a[mi][3], pa + offA[mi] + kk * 2);
            uint32_t b[NF][2];
#pragma unroll
            for (int q = 0; q < NF / 2; q++)
                ldm4(b[2 * q][0], b[2 * q][1], b[2 * q + 1][0], b[2 * q + 1][1],
                     pb + offB[q] + kk * 2);
#pragma unroll
            for (int mi = 0; mi < MF; mi++)
#pragma unroll
                for (int nj = 0; nj < NF; nj++)
                    mma16816(acc[mi][nj], a[mi], b[nj]);
        }
    }

    const int er = lane >> 2;
    const int ec = (lane & 3) * 2;
#pragma unroll
    for (int mi = 0; mi < MF; mi++) {
#pragma unroll
        for (int nj = 0; nj < NF; nj++) {
            int m = m0 + wm * WTM + mi * 16 + er;
            int n = n0 + wn * WTN + nj * 8 + ec;
            float* c = acc[mi][nj];
            epi_write<0>(m,     n,     c[0], bias, nullptr, 0, z);
            epi_write<0>(m,     n + 1, c[1], bias, nullptr, 0, z);
            epi_write<0>(m + 8, n,     c[2], bias, nullptr, 0, z);
            epi_write<0>(m + 8, n + 1, c[3], bias, nullptr, 0, z);
        }
    }
}

#define SMEM_XPROJ (3 * (128 + 128) * (64 + 8) * 2)   // 110592
#define SMEM_REC   (4 * (64 + 64) * (64 + 8) * 2)     // 73728 (max of both phases)

// ---------------- host launcher (graph-capturable, allocation-free) ----------------
extern "C" void kernel_launch(void* const* d_in, const int* in_sizes, int n_in,
                              void* d_out, int out_size)
{
    const float* txt  = (const float*)d_in[0];
    const float* W_iu = (const float*)d_in[1];
    const float* b_iu = (const float*)d_in[2];
    const float* W_hu = (const float*)d_in[3];
    const float* b_hu = (const float*)d_in[4];
    const float* W_ir = (const float*)d_in[5];
    const float* b_ir = (const float*)d_in[6];
    const float* W_hr = (const float*)d_in[7];
    const float* b_hr = (const float*)d_in[8];
    const float* W_i  = (const float*)d_in[9];
    const float* b_i  = (const float*)d_in[10];
    const float* W_h  = (const float*)d_in[11];
    const float* b_h  = (const float*)d_in[12];
    float* out = (float*)d_out;

    cudaFuncSetAttribute((const void*)xproj_gemm<128, 128, 64, 3, 4, 2>,
                         cudaFuncAttributeMaxDynamicSharedMemorySize, SMEM_XPROJ);
    cudaFuncSetAttribute((const void*)rec_persistent,
                         cudaFuncAttributeMaxDynamicSharedMemorySize, SMEM_REC);

    // conversions
    conv_split_A<<<(NTOK * EMB / 2) / 256, 256>>>(txt);
    conv_split_B<<<(EMB * EMB / 2) / 256, 256>>>(W_iu, 0);
    conv_split_B<<<(EMB * EMB / 2) / 256, 256>>>(W_ir, 1);
    conv_split_B<<<(EMB * EMB / 2) / 256, 256>>>(W_i,  2);
    conv_split_B<<<(EMB * EMB / 2) / 256, 256>>>(W_hu, 3);
    conv_split_B<<<(EMB * EMB / 2) / 256, 256>>>(W_hr, 4);
    conv_split_B<<<(EMB * EMB / 2) / 256, 256>>>(W_h,  5);
    bcat_kernel<<<(2 * EMB) / 256, 256>>>(b_hu, b_hr);

    // x-side projections
    xproj_gemm<128, 128, 64, 3, 4, 2>
        <<<dim3(NTOK / 128, EMB / 128, 3), 256, SMEM_XPROJ>>>(b_iu, b_ir, b_i);

    // h0
    h0_kernel<<<(BATCH * EMB) / 256, 256>>>(out);

    // full recurrence in ONE persistent launch
    rec_persistent<<<RCTAS, 128, SMEM_REC>>>(b_h, out);
}

// round 8
// speedup vs baseline: 2.2201x; 1.0718x over previous
#include <cuda_runtime.h>
#include <cuda_bf16.h>
#include <math.h>
#include <stdint.h>

#define EMB   1024
#define STEPS 64
#define BATCH 256
#define NTOK  (BATCH * STEPS)
#define KS    2048   // stored split K:  [hi | lo]
#define KV    3072   // virtual K: seg0 Ah*Bh, seg1 Al*Bh, seg2 Ah*Bl
#define RCTAS 128    // persistent recurrence CTAs (1/SM, co-resident)

// ---------------- static device scratch (allocation-free) ----------------
__device__ __align__(128) __nv_bfloat16 g_txtp[(size_t)NTOK * KS];
__device__ __align__(128) __nv_bfloat16 g_Wx[3ull * EMB * KS];     // W_iu, W_ir, W_i
__device__ __align__(128) __nv_bfloat16 g_Wcat[2ull * EMB * KS];   // [W_hu; W_hr]
__device__ __align__(128) __nv_bfloat16 g_Whp[(size_t)EMB * KS];
__device__ __align__(128) __nv_bfloat16 g_hp[BATCH * KS];
__device__ __align__(128) __nv_bfloat16 g_rhp[BATCH * KS];
__device__ float g_Ziu[(size_t)NTOK * EMB];
__device__ float g_Zir[(size_t)NTOK * EMB];
__device__ float g_Zi [(size_t)NTOK * EMB];
__device__ float g_h[BATCH * EMB];
__device__ float g_u[BATCH * EMB];
__device__ float g_bcat[2 * EMB];
__device__ unsigned g_arrive = 0;
__device__ unsigned g_gen = 0;

// ---------------- helpers ----------------
__device__ __forceinline__ uint32_t su32(const void* p) {
    return (uint32_t)__cvta_generic_to_shared(p);
}
__device__ __forceinline__ void cpa16(uint32_t s, const void* g) {
    asm volatile("cp.async.cg.shared.global [%0], [%1], 16;\n" :: "r"(s), "l"(g));
}
__device__ __forceinline__ void ldm4(uint32_t& r0, uint32_t& r1, uint32_t& r2, uint32_t& r3, uint32_t a) {
    asm volatile("ldmatrix.sync.aligned.m8n8.x4.shared.b16 {%0,%1,%2,%3}, [%4];\n"
                 : "=r"(r0), "=r"(r1), "=r"(r2), "=r"(r3) : "r"(a));
}
__device__ __forceinline__ void mma16816(float* c, const uint32_t* a, const uint32_t* b) {
    asm volatile("mma.sync.aligned.m16n8k16.row.col.f32.bf16.bf16.f32 "
                 "{%0,%1,%2,%3},{%4,%5,%6,%7},{%8,%9},{%0,%1,%2,%3};\n"
                 : "+f"(c[0]), "+f"(c[1]), "+f"(c[2]), "+f"(c[3])
                 : "r"(a[0]), "r"(a[1]), "r"(a[2]), "r"(a[3]), "r"(b[0]), "r"(b[1]));
}
__device__ __forceinline__ void split2(float x, __nv_bfloat16& hi, __nv_bfloat16& lo) {
    hi = __float2bfloat16(x);
    lo = __float2bfloat16(x - __bfloat162float(hi));
}
__device__ __forceinline__ float sigmoid_f(float x) { return 1.0f / (1.0f + expf(-x)); }

// Grid-wide barrier (all RCTAS CTAs co-resident: 1 CTA/SM, RCTAS <= 148)
__device__ __forceinline__ void grid_barrier() {
    __syncthreads();
    if (threadIdx.x == 0) {
        __threadfence();
        unsigned gen = *(volatile unsigned*)&g_gen;
        unsigned old = atomicAdd(&g_arrive, 1);
        if (old == RCTAS - 1) {
            g_arrive = 0;
            __threadfence();
            atomicAdd(&g_gen, 1);
        } else {
            while (*(volatile unsigned*)&g_gen == gen) { __nanosleep(64); }
        }
        __threadfence();
    }
    __syncthreads();
}

// ---------------- conversion kernels ----------------
__global__ void conv_split_A(const float* __restrict__ src) {
    int i = blockIdx.x * blockDim.x + threadIdx.x;
    int row = i >> 9;
    int c2  = (i & 511) << 1;
    float2 v = ((const float2*)src)[i];
    __nv_bfloat16 h0, l0, h1, l1;
    split2(v.x, h0, l0); split2(v.y, h1, l1);
    __nv_bfloat162 hi2; hi2.x = h0; hi2.y = h1;
    __nv_bfloat162 lo2; lo2.x = l0; lo2.y = l1;
    size_t b = (size_t)row * KS + c2;
    *(__nv_bfloat162*)&g_txtp[b]        = hi2;
    *(__nv_bfloat162*)&g_txtp[b + 1024] = lo2;
}
__global__ void conv_split_B(const float* __restrict__ src, int which) {
    int i = blockIdx.x * blockDim.x + threadIdx.x;
    int row = i >> 9;
    int c2  = (i & 511) << 1;
    __nv_bfloat16* dst;
    switch (which) {
        case 0: dst = g_Wx; break;
        case 1: dst = g_Wx + (size_t)EMB * KS; break;
        case 2: dst = g_Wx + 2ull * EMB * KS; break;
        case 3: dst = g_Wcat; break;
        case 4: dst = g_Wcat + (size_t)EMB * KS; break;
        default: dst = g_Whp; break;
    }
    float2 v = ((const float2*)src)[i];
    __nv_bfloat16 h0, l0, h1, l1;
    split2(v.x, h0, l0); split2(v.y, h1, l1);
    __nv_bfloat162 hi2; hi2.x = h0; hi2.y = h1;
    __nv_bfloat162 lo2; lo2.x = l0; lo2.y = l1;
    size_t b = (size_t)row * KS + c2;
    *(__nv_bfloat162*)&dst[b]        = hi2;
    *(__nv_bfloat162*)&dst[b + 1024] = lo2;
}
__global__ void bcat_kernel(const float* __restrict__ b_hu, const float* __restrict__ b_hr) {
    int i = blockIdx.x * blockDim.x + threadIdx.x;
    g_bcat[i] = (i < EMB) ? b_hu[i] : b_hr[i - EMB];
}
__global__ void h0_kernel(float* __restrict__ out) {
    int e = blockIdx.x * blockDim.x + threadIdx.x;
    int b = e >> 10, j = e & 1023;
    size_t zrow = (size_t)b * STEPS * EMB + j;
    float h = tanhf(g_Zi[zrow]);
    g_h[e] = h;
    out[zrow] = h;
    __nv_bfloat16 hi, lo; split2(h, hi, lo);
    size_t bb = (size_t)b * KS + j;
    g_hp[bb] = hi; g_hp[bb + 1024] = lo;
}

// ---------------- epilogues ----------------
template<int EPI>
__device__ __forceinline__ void epi_write(int m, int n, float v, const float* bias,
                                          float* out, int t, int z) {
    if constexpr (EPI == 0) {
        float* Z = (z == 0) ? g_Ziu : (z == 1) ? g_Zir : g_Zi;
        Z[(size_t)m * EMB + n] = v + bias[n];
    } else if constexpr (EPI == 1) {
        size_t zrow = ((size_t)m * STEPS + t) * EMB;
        if (n < EMB) {
            float u = sigmoid_f(v + g_Ziu[zrow + n] + g_bcat[n]);
            g_u[m * EMB + n] = u;
        } else {
            int nn = n - EMB;
            float r = sigmoid_f(v + g_Zir[zrow + nn] + g_bcat[n]);
            float rh = r * g_h[m * EMB + nn];
            __nv_bfloat16 hi, lo; split2(rh, hi, lo);
            size_t b = (size_t)m * KS + nn;
            g_rhp[b] = hi; g_rhp[b + 1024] = lo;
        }
    } else {
        size_t zrow = ((size_t)m * STEPS + t) * EMB;
        float cand = tanhf(v + g_Zi[zrow + n] + bias[n]);
        float u = g_u[m * EMB + n];
        float h = g_h[m * EMB + n];
        float hn = u * h + (1.0f - u) * cand;
        out[zrow + n] = hn;
        g_h[m * EMB + n] = hn;
        __nv_bfloat16 hi, lo; split2(hn, hi, lo);
        size_t b = (size_t)m * KS + n;
        g_hp[b] = hi; g_hp[b + 1024] = lo;
    }
}

// ---------------- tile-GEMM over virtual K (device fn, WM*WN*32 threads) --------
template<int BM, int BN, int WM, int WN, int EPI>
__device__ __forceinline__ void tile_gemm(const __nv_bfloat16* __restrict__ Ag,
                                          const __nv_bfloat16* __restrict__ Bg,
                                          __nv_bfloat16* sm,
                                          const float* bias, float* out, int t,
                                          int m0, int n0)
{
    constexpr int THREADS = WM * WN * 32;
    constexpr int BK = 64;
    constexpr int S  = 4;
    constexpr int LDS = BK + 8;
    constexpr int WTM = BM / WM;
    constexpr int WTN = BN / WN;
    constexpr int MF = WTM / 16;
    constexpr int NF = WTN / 8;
    constexpr int NK = KV / BK;

    __nv_bfloat16* Asm = sm;
    __nv_bfloat16* Bsm = sm + (size_t)S * BM * LDS;

    const int tid  = threadIdx.x;
    const int lane = tid & 31;
    const int wid  = tid >> 5;
    const int wm   = wid % WM;
    const int wn   = wid / WM;

    float acc[MF][NF][4];
#pragma unroll
    for (int mi = 0; mi < MF; mi++)
#pragma unroll
        for (int nj = 0; nj < NF; nj++)
#pragma unroll
            for (int q = 0; q < 4; q++) acc[mi][nj][q] = 0.0f;

    uint32_t offA[MF];
    {
        const int arow = wm * WTM + (lane & 15);
        const int acol = (lane >> 4) << 3;
#pragma unroll
        for (int mi = 0; mi < MF; mi++)
            offA[mi] = ((arow + mi * 16) * LDS + acol) * 2;
    }
    uint32_t offB[NF / 2];
    {
        const int g = lane >> 3;
        const int brow = wn * WTN + (lane & 7) + ((g >> 1) << 3);
        const int bcol = (g & 1) << 3;
#pragma unroll
        for (int p = 0; p < NF / 2; p++)
            offB[p] = ((brow + p * 16) * LDS + bcol) * 2;
    }

    auto load_stage = [&](int s, int kt) {
        const int k0 = kt * BK;
        const int ak = (k0 < 2048) ? k0 : k0 - 2048;
        const int bk = (k0 < 1024) ? k0 : k0 - 1024;
        __nv_bfloat16* a = Asm + (size_t)s * BM * LDS;
        __nv_bfloat16* b = Bsm + (size_t)s * BN * LDS;
        constexpr int SEG = BK / 8;
        constexpr int CA = (BM * SEG) / THREADS;
#pragma unroll
        for (int it = 0; it < CA; ++it) {
            int c = tid + it * THREADS;
            int row = c / SEG, seg = c % SEG;
            cpa16(su32(a + row * LDS + seg * 8), Ag + (size_t)row * KS + ak + seg * 8);
        }
        constexpr int CB = (BN * SEG) / THREADS;
#pragma unroll
        for (int it = 0; it < CB; ++it) {
            int c = tid + it * THREADS;
            int row = c / SEG, seg = c % SEG;
            cpa16(su32(b + row * LDS + seg * 8), Bg + (size_t)row * KS + bk + seg * 8);
        }
    };

#pragma unroll
    for (int s = 0; s < S - 1; ++s) {
        load_stage(s, s);
        asm volatile("cp.async.commit_group;\n" ::);
    }

    for (int kt = 0; kt < NK; ++kt) {
        if (kt + S - 2 < NK) asm volatile("cp.async.wait_group %0;\n" :: "n"(S - 2));
        else                 asm volatile("cp.async.wait_group 0;\n" ::);
        __syncthreads();

        const int nx = kt + S - 1;
        if (nx < NK) {
            load_stage(nx % S, nx);
            asm volatile("cp.async.commit_group;\n" ::);
        }

        const uint32_t pa = su32(Asm + (size_t)(kt % S) * BM * LDS);
        const uint32_t pb = su32(Bsm + (size_t)(kt % S) * BN * LDS);
#pragma unroll
        for (int kk = 0; kk < BK; kk += 16) {
            uint32_t a[MF][4];
#pragma unroll
            for (int mi = 0; mi < MF; mi++)
                ldm4(a[mi][0], a[mi][1], a[mi][2], a[mi][3], pa + offA[mi] + kk * 2);
            uint32_t b[NF][2];
#pragma unroll
            for (int q = 0; q < NF / 2; q++)
                ldm4(b[2 * q][0], b[2 * q][1], b[2 * q + 1][0], b[2 * q + 1][1],
                     pb + offB[q] + kk * 2);
#pragma unroll
            for (int mi = 0; mi < MF; mi++)
#pragma unroll
                for (int nj = 0; nj < NF; nj++)
                    mma16816(acc[mi][nj], a[mi], b[nj]);
        }
    }

    const int er = lane >> 2;
    const int ec = (lane & 3) * 2;
#pragma unroll
    for (int mi = 0; mi < MF; mi++) {
#pragma unroll
        for (int nj = 0; nj < NF; nj++) {
            int m = m0 + wm * WTM + mi * 16 + er;
            int n = n0 + wn * WTN + nj * 8 + ec;
            float* c = acc[mi][nj];
            epi_write<EPI>(m,     n,     c[0], bias, out, t, 0);
            epi_write<EPI>(m,     n + 1, c[1], bias, out, t, 0);
            epi_write<EPI>(m + 8, n,     c[2], bias, out, t, 0);
            epi_write<EPI>(m + 8, n + 1, c[3], bias, out, t, 0);
        }
    }
}

// ---------------- persistent recurrence kernel (256 threads: 2 warps/SMSP) ------
__global__ void __launch_bounds__(256)
rec_persistent(const float* __restrict__ b_h, float* __restrict__ out)
{
    extern __shared__ __align__(16) __nv_bfloat16 sm[];
    const int bid = blockIdx.x;
    const int mA = (bid & 3) * 64, nA = (bid >> 2) * 64;   // gates: 4 x 32 tiles
    const int mB = (bid & 3) * 64, nB = (bid >> 2) * 32;   // cand : 4 x 32 tiles

    for (int t = 1; t < STEPS; ++t) {
        // phase A: gates (u, r) from h — 8 warps, WM=2 x WN=4
        tile_gemm<64, 64, 2, 4, 1>(g_hp + (size_t)mA * KS, g_Wcat + (size_t)nA * KS,
                                   sm, nullptr, nullptr, t, mA, nA);
        grid_barrier();
        // phase B: candidate + blend from r*h — 8 warps, WM=4 x WN=2
        tile_gemm<64, 32, 4, 2, 2>(g_rhp + (size_t)mB * KS, g_Whp + (size_t)nB * KS,
                                   sm, b_h, out, t, mB, nB);
        if (t < STEPS - 1) grid_barrier();
    }
}

// ---------------- xproj multistage GEMM ----------------
template<int BM, int BN, int BK, int S, int WM, int WN>
__global__ void __launch_bounds__(WM * WN * 32)
xproj_gemm(const float* __restrict__ bias0, const float* __restrict__ bias1,
           const float* __restrict__ bias2)
{
    constexpr int THREADS = WM * WN * 32;
    constexpr int LDS = BK + 8;
    constexpr int WTM = BM / WM;
    constexpr int WTN = BN / WN;
    constexpr int MF = WTM / 16;
    constexpr int NF = WTN / 8;
    constexpr int NK = KV / BK;

    extern __shared__ __align__(16) __nv_bfloat16 sm[];
    __nv_bfloat16* Asm = sm;
    __nv_bfloat16* Bsm = sm + (size_t)S * BM * LDS;

    const int tid  = threadIdx.x;
    const int lane = tid & 31;
    const int wid  = tid >> 5;
    const int wm   = wid % WM;
    const int wn   = wid / WM;
    const int m0   = blockIdx.x * BM;
    const int n0   = blockIdx.y * BN;
    const int z    = blockIdx.z;

    const __nv_bfloat16* Ag = g_txtp + (size_t)m0 * KS;
    const __nv_bfloat16* Bg = g_Wx + (size_t)z * EMB * KS + (size_t)n0 * KS;
    const float* bias = (z == 0) ? bias0 : (z == 1) ? bias1 : bias2;

    float acc[MF][NF][4];
#pragma unroll
    for (int mi = 0; mi < MF; mi++)
#pragma unroll
        for (int nj = 0; nj < NF; nj++)
#pragma unroll
            for (int q = 0; q < 4; q++) acc[mi][nj][q] = 0.0f;

    uint32_t offA[MF];
    {
        const int arow = wm * WTM + (lane & 15);
        const int acol = (lane >> 4) << 3;
#pragma unroll
        for (int mi = 0; mi < MF; mi++)
            offA[mi] = ((arow + mi * 16) * LDS + acol) * 2;
    }
    uint32_t offB[NF / 2];
    {
        const int g = lane >> 3;
        const int brow = wn * WTN + (lane & 7) + ((g >> 1) << 3);
        const int bcol = (g & 1) << 3;
#pragma unroll
        for (int p = 0; p < NF / 2; p++)
            offB[p] = ((brow + p * 16) * LDS + bcol) * 2;
    }

    auto load_stage = [&](int s, int kt) {
        const int k0 = kt * BK;
        const int ak = (k0 < 2048) ? k0 : k0 - 2048;
        const int bk = (k0 < 1024) ? k0 : k0 - 1024;
        __nv_bfloat16* a = Asm + (size_t)s * BM * LDS;
        __nv_bfloat16* b = Bsm + (size_t)s * BN * LDS;
        constexpr int SEG = BK / 8;
        constexpr int CA = (BM * SEG) / THREADS;
#pragma unroll
        for (int it = 0; it < CA; ++it) {
            int c = tid + it * THREADS;
            int row = c / SEG, seg = c % SEG;
            cpa16(su32(a + row * LDS + seg * 8), Ag + (size_t)row * KS + ak + seg * 8);
        }
        constexpr int CB = (BN * SEG) / THREADS;
#pragma unroll
        for (int it = 0; it < CB; ++it) {
            int c = tid + it * THREADS;
            int row = c / SEG, seg = c % SEG;
            cpa16(su32(b + row * LDS + seg * 8), Bg + (size_t)row * KS + bk + seg * 8);
        }
    };

#pragma unroll
    for (int s = 0; s < S - 1; ++s) {
        load_stage(s, s);
        asm volatile("cp.async.commit_group;\n" ::);
    }

    for (int kt = 0; kt < NK; ++kt) {
        if (kt + S - 2 < NK) asm volatile("cp.async.wait_group %0;\n" :: "n"(S - 2));
        else                 asm volatile("cp.async.wait_group 0;\n" ::);
        __syncthreads();

        const int nx = kt + S - 1;
        if (nx < NK) {
            load_stage(nx % S, nx);
            asm volatile("cp.async.commit_group;\n" ::);
        }

        const uint32_t pa = su32(Asm + (size_t)(kt % S) * BM * LDS);
        const uint32_t pb = su32(Bsm + (size_t)(kt % S) * BN * LDS);
#pragma unroll
        for (int kk = 0; kk < BK; kk += 16) {
            uint32_t a[MF][4];
#pragma unroll
            for (int mi = 0; mi < MF; mi++)
                ldm4(a[mi][0], a[mi][1], a[mi][2], a[mi][3], pa + offA[mi] + kk * 2);
            uint32_t b[NF][2];
#pragma unroll
            for (int q = 0; q < NF / 2; q++)
                ldm4(b[2 * q][0], b[2 * q][1], b[2 * q + 1][0], b[2 * q + 1][1],
                     pb + offB[q] + kk * 2);
#pragma unroll
            for (int mi = 0; mi < MF; mi++)
#pragma unroll
                for (int nj = 0; nj < NF; nj++)
                    mma16816(acc[mi][nj], a[mi], b[nj]);
        }
    }

    const int er = lane >> 2;
    const int ec = (lane & 3) * 2;
#pragma unroll
    for (int mi = 0; mi < MF; mi++) {
#pragma unroll
        for (int nj = 0; nj < NF; nj++) {
            int m = m0 + wm * WTM + mi * 16 + er;
            int n = n0 + wn * WTN + nj * 8 + ec;
            float* c = acc[mi][nj];
            epi_write<0>(m,     n,     c[0], bias, nullptr, 0, z);
            epi_write<0>(m,     n + 1, c[1], bias, nullptr, 0, z);
            epi_write<0>(m + 8, n,     c[2], bias, nullptr, 0, z);
            epi_write<0>(m + 8, n + 1, c[3], bias, nullptr, 0, z);
        }
    }
}

#define SMEM_XPROJ (3 * (128 + 128) * (64 + 8) * 2)   // 110592
#define SMEM_REC   (4 * (64 + 64) * (64 + 8) * 2)     // 73728

// ---------------- host launcher (graph-capturable, allocation-free) ----------------
extern "C" void kernel_launch(void* const* d_in, const int* in_sizes, int n_in,
                              void* d_out, int out_size)
{
    const float* txt  = (const float*)d_in[0];
    const float* W_iu = (const float*)d_in[1];
    const float* b_iu = (const float*)d_in[2];
    const float* W_hu = (const float*)d_in[3];
    const float* b_hu = (const float*)d_in[4];
    const float* W_ir = (const float*)d_in[5];
    const float* b_ir = (const float*)d_in[6];
    const float* W_hr = (const float*)d_in[7];
    const float* b_hr = (const float*)d_in[8];
    const float* W_i  = (const float*)d_in[9];
    const float* b_i  = (const float*)d_in[10];
    const float* W_h  = (const float*)d_in[11];
    const float* b_h  = (const float*)d_in[12];
    float* out = (float*)d_out;

    cudaFuncSetAttribute((const void*)xproj_gemm<128, 128, 64, 3, 4, 2>,
                         cudaFuncAttributeMaxDynamicSharedMemorySize, SMEM_XPROJ);
    cudaFuncSetAttribute((const void*)rec_persistent,
                         cudaFuncAttributeMaxDynamicSharedMemorySize, SMEM_REC);

    // conversions
    conv_split_A<<<(NTOK * EMB / 2) / 256, 256>>>(txt);
    conv_split_B<<<(EMB * EMB / 2) / 256, 256>>>(W_iu, 0);
    conv_split_B<<<(EMB * EMB / 2) / 256, 256>>>(W_ir, 1);
    conv_split_B<<<(EMB * EMB / 2) / 256, 256>>>(W_i,  2);
    conv_split_B<<<(EMB * EMB / 2) / 256, 256>>>(W_hu, 3);
    conv_split_B<<<(EMB * EMB / 2) / 256, 256>>>(W_hr, 4);
    conv_split_B<<<(EMB * EMB / 2) / 256, 256>>>(W_h,  5);
    bcat_kernel<<<(2 * EMB) / 256, 256>>>(b_hu, b_hr);

    // x-side projections
    xproj_gemm<128, 128, 64, 3, 4, 2>
        <<<dim3(NTOK / 128, EMB / 128, 3), 256, SMEM_XPROJ>>>(b_iu, b_ir, b_i);

    // h0
    h0_kernel<<<(BATCH * EMB) / 256, 256>>>(out);

    // full recurrence in ONE persistent launch (256 threads/CTA)
    rec_persistent<<<RCTAS, 256, SMEM_REC>>>(b_h, out);
}